// round 10
// baseline (speedup 1.0000x reference)
#include <cuda_runtime.h>

#define NC   100    // num classes
#define NP   64     // features per row
#define NB   444    // accumulate blocks (3 per SM x 148)
#define T    512    // threads per block
#define CAP  112    // per-class bin capacity (rows/block ~4510, mean/class ~45)

// Global scratch (device globals: allocation-free, graph-capture safe).
// Zero-initialized at module load; finalize kernel restores zeros each run.
__device__ float        g_s[NC * NP];   // per-(class,feature) sums
__device__ float        g_rss[NC];      // per-class sum of ||x_i||^2
__device__ unsigned int g_cnt[NC];      // per-class counts

// ---------------------------------------------------------------------------
// Kernel 1: accumulate via block-local class binning.
//   Phase 1 (bin):    thread-per-row; scatter local row idx (uint16) into
//                     per-class bins. 1 shared atomic + 1 STS per row.
//   Phase 2 (gather): warp-per-class; register accumulation (LDG.128/row,
//                     16 lanes per row, 8-row unroll -> 4 indep loads),
//                     halves combined via shfl, direct ATOMG to g_s.
//   Overflow (statistically never): direct global-atomic fallback.
// ---------------------------------------------------------------------------
__global__ void __launch_bounds__(T, 3)
CLIR_accum_kernel(const float* __restrict__ x,
                  const int* __restrict__ t,
                  int n, int rpb) {
    __shared__ unsigned short s_bin[NC * CAP];  // 22.4 KB
    __shared__ unsigned int   s_cnt[NC];
    __shared__ float          s_rss[NC];

    const int tid = threadIdx.x;

    for (int j = tid; j < NC; j += T) { s_cnt[j] = 0u; s_rss[j] = 0.0f; }
    __syncthreads();

    const int block_start = blockIdx.x * rpb;          // multiple of 8
    const int block_end   = min(block_start + rpb, n);
    const int nrow        = max(block_end - block_start, 0);

    // ---------------- Phase 1: bin ----------------
    {
        const int4* __restrict__ t4 = (const int4*)(t + block_start);
        const int n4 = nrow >> 2;
        for (int g = tid; g < n4; g += T) {
            int4 tc = __ldg(&t4[g]);
            int lr = g << 2;
            int cc[4] = {tc.x, tc.y, tc.z, tc.w};
            #pragma unroll
            for (int k = 0; k < 4; ++k) {
                int c = cc[k];
                unsigned p = atomicAdd(&s_cnt[c], 1u);
                if (p < CAP) {
                    s_bin[c * CAP + p] = (unsigned short)(lr + k);
                } else {
                    // statistically-never fallback: direct global atomics
                    const float* row = x + (long long)(block_start + lr + k) * NP;
                    float q = 0.0f;
                    for (int f = 0; f < NP; ++f) {
                        float v = __ldg(&row[f]);
                        atomicAdd(&g_s[c * NP + f], v);
                        q += v * v;
                    }
                    atomicAdd(&s_rss[c], q);
                }
            }
        }
        for (int r = (n4 << 2) + tid; r < nrow; r += T) {
            int c = __ldg(&t[block_start + r]);
            unsigned p = atomicAdd(&s_cnt[c], 1u);
            if (p < CAP) {
                s_bin[c * CAP + p] = (unsigned short)r;
            } else {
                const float* row = x + (long long)(block_start + r) * NP;
                float q = 0.0f;
                for (int f = 0; f < NP; ++f) {
                    float v = __ldg(&row[f]);
                    atomicAdd(&g_s[c * NP + f], v);
                    q += v * v;
                }
                atomicAdd(&s_rss[c], q);
            }
        }
    }
    __syncthreads();

    // ---------------- Phase 2: gather (register accumulation) ----------------
    {
        const int wid  = tid >> 5;
        const int lane = tid & 31;
        const int l16  = lane & 15;
        const int hsel = lane >> 4;      // which row of each pair this lane reads
        const float4* __restrict__ xb =
            (const float4*)x + (long long)block_start * 16;

        for (int c = wid; c < NC; c += (T / 32)) {
            int kk = min((int)s_cnt[c], CAP);
            const unsigned short* bin = &s_bin[c * CAP];

            float s0 = 0.f, s1 = 0.f, s2 = 0.f, s3 = 0.f, q = 0.f;

            int j = 0;
            for (; j + 7 < kk; j += 8) {     // 8 rows/iter -> 4 indep LDG.128
                int liA = bin[j     + hsel];
                int liB = bin[j + 2 + hsel];
                int liC = bin[j + 4 + hsel];
                int liD = bin[j + 6 + hsel];
                float4 a = __ldg(&xb[(long long)liA * 16 + l16]);
                float4 b = __ldg(&xb[(long long)liB * 16 + l16]);
                float4 e = __ldg(&xb[(long long)liC * 16 + l16]);
                float4 d = __ldg(&xb[(long long)liD * 16 + l16]);
                s0 += a.x; s1 += a.y; s2 += a.z; s3 += a.w;
                q  += a.x * a.x + a.y * a.y + a.z * a.z + a.w * a.w;
                s0 += b.x; s1 += b.y; s2 += b.z; s3 += b.w;
                q  += b.x * b.x + b.y * b.y + b.z * b.z + b.w * b.w;
                s0 += e.x; s1 += e.y; s2 += e.z; s3 += e.w;
                q  += e.x * e.x + e.y * e.y + e.z * e.z + e.w * e.w;
                s0 += d.x; s1 += d.y; s2 += d.z; s3 += d.w;
                q  += d.x * d.x + d.y * d.y + d.z * d.z + d.w * d.w;
            }
            for (; j < kk; j += 2) {         // predicated tail (0-7 rows)
                int jj = j + hsel;
                if (jj < kk) {
                    int li = bin[jj];
                    float4 a = __ldg(&xb[(long long)li * 16 + l16]);
                    s0 += a.x; s1 += a.y; s2 += a.z; s3 += a.w;
                    q  += a.x * a.x + a.y * a.y + a.z * a.z + a.w * a.w;
                }
            }

            if (kk) {
                // combine the two half-warps, then 16 lanes ATOMG to global
                s0 += __shfl_xor_sync(0xffffffffu, s0, 16);
                s1 += __shfl_xor_sync(0xffffffffu, s1, 16);
                s2 += __shfl_xor_sync(0xffffffffu, s2, 16);
                s3 += __shfl_xor_sync(0xffffffffu, s3, 16);
                q  += __shfl_xor_sync(0xffffffffu, q, 16);
                q  += __shfl_xor_sync(0xffffffffu, q, 8);
                q  += __shfl_xor_sync(0xffffffffu, q, 4);
                q  += __shfl_xor_sync(0xffffffffu, q, 2);
                q  += __shfl_xor_sync(0xffffffffu, q, 1);
                if (hsel == 0) {
                    int fb = c * NP + l16 * 4;
                    atomicAdd(&g_s[fb + 0], s0);
                    atomicAdd(&g_s[fb + 1], s1);
                    atomicAdd(&g_s[fb + 2], s2);
                    atomicAdd(&g_s[fb + 3], s3);
                }
                if (lane == 0) atomicAdd(&s_rss[c], q);
            }
        }
    }
    __syncthreads();

    // ---------------- Flush per-class scalars to global ----------------
    for (int j = tid; j < NC; j += T) {
        float r = s_rss[j];
        if (r != 0.0f) atomicAdd(&g_rss[j], r);
        unsigned cgt = s_cnt[j];
        if (cgt) atomicAdd(&g_cnt[j], cgt);
    }
}

// ---------------------------------------------------------------------------
// Kernel 2: finalize + self-reset (restores zeros for the next replay).
//   result = (1/NC) * sum_c [ (rss_c - sum_p s_cp^2 / n_c) / (n_c - 1) ]
// ---------------------------------------------------------------------------
__global__ void CLIR_final_kernel(float* __restrict__ out) {
    __shared__ float red[256];
    float acc = 0.0f;

    for (int j = threadIdx.x; j < NC * NP; j += blockDim.x) {
        int c = j >> 6;
        float ncf = (float)g_cnt[c];
        float s = g_s[j];
        acc -= (s * s) / (ncf * (ncf - 1.0f));
    }
    for (int c = threadIdx.x; c < NC; c += blockDim.x) {
        float ncf = (float)g_cnt[c];
        acc += g_rss[c] / (ncf - 1.0f);
    }

    red[threadIdx.x] = acc;
    __syncthreads();   // all reads of g_* complete before reset
    for (int off = 128; off > 0; off >>= 1) {
        if (threadIdx.x < off) red[threadIdx.x] += red[threadIdx.x + off];
        __syncthreads();
    }
    if (threadIdx.x == 0) out[0] = red[0] / (float)NC;

    // self-reset for the next graph replay
    for (int j = threadIdx.x; j < NC * NP; j += blockDim.x) g_s[j] = 0.0f;
    for (int j = threadIdx.x; j < NC; j += blockDim.x) { g_rss[j] = 0.0f; g_cnt[j] = 0u; }
}

// ---------------------------------------------------------------------------
// Launch
// ---------------------------------------------------------------------------
extern "C" void kernel_launch(void* const* d_in, const int* in_sizes, int n_in,
                              void* d_out, int out_size) {
    const float* x = (const float*)d_in[0];
    const int*   t = (const int*)d_in[1];
    int n = in_sizes[1];

    float* out = (float*)d_out;

    int rpb = (((n + NB - 1) / NB) + 7) & ~7;   // rows per block, multiple of 8

    CLIR_accum_kernel<<<NB, T>>>(x, t, n, rpb);
    CLIR_final_kernel<<<1, 256>>>(out);
}